// round 5
// baseline (speedup 1.0000x reference)
#include <cuda_runtime.h>
#include <math.h>

#define NN 50000
#define NE 1600000
#define F0 512
#define F1 128
#define F2 40
#define NB_SCAN ((NN + 255) / 256)   // 196

// ---- scratch (static device globals; no allocation allowed) ----
__device__ int   g_is64;
__device__ int   g_src   [NE];
__device__ int   g_dst   [NE];
__device__ float g_dinv[NN];
__device__ int   g_cnt   [NN];
__device__ int   g_off   [NN + 1];
__device__ int   g_cursor[NN];
__device__ int   g_bsum  [NB_SCAN];
__device__ int   g_bbase [NB_SCAN];
__device__ int   g_csr   [NE];
__device__ float g_csrn  [NE];
__device__ float g_h1  [(size_t)NN * F1];
__device__ float g_agg1[(size_t)NN * F1];
__device__ float g_h2  [(size_t)NN * F2];

// ---- dtype detection + edge conversion ----
// If data is int64, the high word of each little-endian 8-byte slot is 0
// (values in [0, 50000)). If int32, those words are random edge indices.
__global__ void k_detect(const unsigned int* __restrict__ raw) {
    int is64 = 1;
    for (int i = 0; i < 64; i++)
        if (raw[2 * i + 1] != 0u) { is64 = 0; break; }
    g_is64 = is64;
}

__global__ void k_convert(const void* __restrict__ eiraw) {
    int i = blockIdx.x * blockDim.x + threadIdx.x;
    if (i >= 2 * NE) return;
    int v;
    if (g_is64) v = (int)((const long long*)eiraw)[i];
    else        v = ((const int*)eiraw)[i];
    if (i < NE) g_src[i] = v;
    else        g_dst[i - NE] = v;
}

// ---- CSR build ----
__global__ void k_zero_cnt() {
    int i = blockIdx.x * blockDim.x + threadIdx.x;
    if (i < NN) g_cnt[i] = 0;
}

__global__ void k_count() {
    int e = blockIdx.x * blockDim.x + threadIdx.x;
    if (e < NE) atomicAdd(&g_cnt[g_dst[e]], 1);
}

// block-local exclusive scan (256 elems/block) + block sums
__global__ void k_scanA() {
    __shared__ int s[256];
    int t = threadIdx.x;
    int i = blockIdx.x * 256 + t;
    int v = (i < NN) ? g_cnt[i] : 0;
    s[t] = v;
    __syncthreads();
    #pragma unroll
    for (int off = 1; off < 256; off <<= 1) {
        int u = (t >= off) ? s[t - off] : 0;
        __syncthreads();
        s[t] += u;
        __syncthreads();
    }
    if (i < NN) g_off[i] = s[t] - v;          // exclusive, local
    if (t == 255) g_bsum[blockIdx.x] = s[255];
}

__global__ void k_scanB() {
    __shared__ int s[256];
    int t = threadIdx.x;
    int v = (t < NB_SCAN) ? g_bsum[t] : 0;
    s[t] = v;
    __syncthreads();
    #pragma unroll
    for (int off = 1; off < 256; off <<= 1) {
        int u = (t >= off) ? s[t - off] : 0;
        __syncthreads();
        s[t] += u;
        __syncthreads();
    }
    if (t < NB_SCAN) g_bbase[t] = s[t] - v;   // exclusive
}

// finalize offsets, init cursors, dinv = rsqrt(indeg + self-loop)
__global__ void k_scanC() {
    int i = blockIdx.x * blockDim.x + threadIdx.x;
    if (i < NN) {
        int val = g_off[i] + g_bbase[i >> 8];
        g_off[i]    = val;
        g_cursor[i] = val;
        g_dinv[i]   = rsqrtf((float)(g_cnt[i] + 1));
    }
    if (i == 0) g_off[NN] = NE;
}

// fill CSR adjacency + precomputed per-edge norm
__global__ void k_fill() {
    int e = blockIdx.x * blockDim.x + threadIdx.x;
    if (e >= NE) return;
    int s = g_src[e];
    int d = g_dst[e];
    int pos = atomicAdd(&g_cursor[d], 1);
    g_csr[pos]  = s;
    g_csrn[pos] = g_dinv[s] * g_dinv[d];
}

// ---- GEMM1: h1 = x @ W1  (BM=128, BN=128, BK=16, 256 thr, 8x8 microtile) ----
__global__ void __launch_bounds__(256) k_gemm1(const float* __restrict__ A,
                                               const float* __restrict__ W) {
    __shared__ float sA[16][132];
    __shared__ float sB[16][128];
    const int tid = threadIdx.x;
    const int blockRow = blockIdx.x * 128;
    const int tx = tid & 15;
    const int ty = tid >> 4;

    float acc[8][8];
    #pragma unroll
    for (int i = 0; i < 8; i++)
        #pragma unroll
        for (int j = 0; j < 8; j++) acc[i][j] = 0.f;

    for (int k0 = 0; k0 < F0; k0 += 16) {
        #pragma unroll
        for (int i = 0; i < 2; i++) {
            int id  = tid + i * 256;
            int row = id >> 2;
            int c   = id & 3;
            int gr  = blockRow + row;
            float4 v = make_float4(0.f, 0.f, 0.f, 0.f);
            if (gr < NN)
                v = *(const float4*)(A + (size_t)gr * F0 + k0 + c * 4);
            sA[c * 4 + 0][row] = v.x;
            sA[c * 4 + 1][row] = v.y;
            sA[c * 4 + 2][row] = v.z;
            sA[c * 4 + 3][row] = v.w;
        }
        #pragma unroll
        for (int i = 0; i < 2; i++) {
            int id = tid + i * 256;
            int kk = id >> 5;
            int c  = id & 31;
            *(float4*)(&sB[kk][c * 4]) =
                *(const float4*)(W + (size_t)(k0 + kk) * F1 + c * 4);
        }
        __syncthreads();

        #pragma unroll
        for (int kk = 0; kk < 16; kk++) {
            float a[8], b[8];
            #pragma unroll
            for (int j = 0; j < 8; j++) a[j] = sA[kk][ty * 8 + j];
            #pragma unroll
            for (int j = 0; j < 8; j++) b[j] = sB[kk][tx * 8 + j];
            #pragma unroll
            for (int i = 0; i < 8; i++)
                #pragma unroll
                for (int j = 0; j < 8; j++)
                    acc[i][j] += a[i] * b[j];
        }
        __syncthreads();
    }

    #pragma unroll
    for (int i = 0; i < 8; i++) {
        int gr = blockRow + ty * 8 + i;
        if (gr >= NN) continue;
        #pragma unroll
        for (int j = 0; j < 8; j += 4) {
            int col = tx * 8 + j;
            float4 v = make_float4(acc[i][j], acc[i][j+1], acc[i][j+2], acc[i][j+3]);
            *(float4*)(g_h1 + (size_t)gr * F1 + col) = v;
        }
    }
}

// ---- gather layer 1: one warp per dst node, 128 feats (f4/lane) ----
__global__ void k_gather1() {
    int g = blockIdx.x * blockDim.x + threadIdx.x;
    int node = g >> 5;
    int lane = g & 31;
    if (node >= NN) return;

    float dd = g_dinv[node];
    float4 acc = *(const float4*)(g_h1 + (size_t)node * F1 + lane * 4);
    float self = dd * dd;
    acc.x *= self; acc.y *= self; acc.z *= self; acc.w *= self;

    int beg = g_off[node];
    int end = g_off[node + 1];
    int   s_next = (beg < end) ? __ldg(g_csr  + beg) : 0;
    float n_next = (beg < end) ? __ldg(g_csrn + beg) : 0.f;
    for (int j = beg; j < end; j++) {
        int   s    = s_next;
        float norm = n_next;
        if (j + 1 < end) {
            s_next = __ldg(g_csr  + j + 1);
            n_next = __ldg(g_csrn + j + 1);
        }
        float4 v = *(const float4*)(g_h1 + (size_t)s * F1 + lane * 4);
        acc.x += v.x * norm;
        acc.y += v.y * norm;
        acc.z += v.z * norm;
        acc.w += v.w * norm;
    }
    *(float4*)(g_agg1 + (size_t)node * F1 + lane * 4) = acc;
}

// ---- GEMM2: h2 = relu(agg1 + b1) @ W2 (BM=64, N=40, BK=64, 128 thr) ----
__global__ void __launch_bounds__(128) k_gemm2(const float* __restrict__ W2,
                                               const float* __restrict__ b1) {
    __shared__ float sW[F1 * F2];
    __shared__ float sBias[F1];
    __shared__ float sA[64][65];

    const int tid = threadIdx.x;
    const int rowBase = blockIdx.x * 64;
    const int tx = tid & 7;
    const int ty = tid >> 3;

    for (int i = tid; i < F1 * F2; i += 128) sW[i] = W2[i];
    if (tid < F1) sBias[tid] = b1[tid];
    __syncthreads();

    float acc[4][5];
    #pragma unroll
    for (int j = 0; j < 4; j++)
        #pragma unroll
        for (int i = 0; i < 5; i++) acc[j][i] = 0.f;

    for (int kt = 0; kt < F1; kt += 64) {
        #pragma unroll
        for (int i = 0; i < 8; i++) {
            int f4  = tid + i * 128;
            int row = f4 >> 4;
            int c   = f4 & 15;
            int k   = kt + c * 4;
            int r   = rowBase + row;
            float4 v = make_float4(0.f, 0.f, 0.f, 0.f);
            if (r < NN)
                v = *(const float4*)(g_agg1 + (size_t)r * F1 + k);
            v.x = fmaxf(v.x + sBias[k + 0], 0.f);
            v.y = fmaxf(v.y + sBias[k + 1], 0.f);
            v.z = fmaxf(v.z + sBias[k + 2], 0.f);
            v.w = fmaxf(v.w + sBias[k + 3], 0.f);
            sA[row][c * 4 + 0] = v.x;
            sA[row][c * 4 + 1] = v.y;
            sA[row][c * 4 + 2] = v.z;
            sA[row][c * 4 + 3] = v.w;
        }
        __syncthreads();

        #pragma unroll 16
        for (int kk = 0; kk < 64; kk++) {
            float a[4], b[5];
            #pragma unroll
            for (int j = 0; j < 4; j++) a[j] = sA[ty * 4 + j][kk];
            #pragma unroll
            for (int i = 0; i < 5; i++) b[i] = sW[(kt + kk) * F2 + tx * 5 + i];
            #pragma unroll
            for (int j = 0; j < 4; j++)
                #pragma unroll
                for (int i = 0; i < 5; i++)
                    acc[j][i] += a[j] * b[i];
        }
        __syncthreads();
    }

    #pragma unroll
    for (int j = 0; j < 4; j++) {
        int r = rowBase + ty * 4 + j;
        if (r >= NN) continue;
        #pragma unroll
        for (int i = 0; i < 5; i++)
            g_h2[(size_t)r * F2 + tx * 5 + i] = acc[j][i];
    }
}

// ---- gather layer 2 + bias + log_softmax fused: one warp per node ----
// lanes 0..9 each hold one float4 chunk (10*4 = 40 classes)
__global__ void k_gather2_lsm(const float* __restrict__ b2,
                              float* __restrict__ out) {
    int g = blockIdx.x * blockDim.x + threadIdx.x;
    int node = g >> 5;
    int lane = g & 31;
    if (node >= NN) return;

    bool act = lane < 10;
    float dd = g_dinv[node];
    float4 acc = make_float4(0.f, 0.f, 0.f, 0.f);
    if (act) {
        acc = *(const float4*)(g_h2 + (size_t)node * F2 + lane * 4);
        float self = dd * dd;
        acc.x *= self; acc.y *= self; acc.z *= self; acc.w *= self;
    }

    int beg = g_off[node];
    int end = g_off[node + 1];
    int   s_next = (beg < end) ? __ldg(g_csr  + beg) : 0;
    float n_next = (beg < end) ? __ldg(g_csrn + beg) : 0.f;
    for (int j = beg; j < end; j++) {
        int   s    = s_next;
        float norm = n_next;
        if (j + 1 < end) {
            s_next = __ldg(g_csr  + j + 1);
            n_next = __ldg(g_csrn + j + 1);
        }
        if (act) {
            float4 v = *(const float4*)(g_h2 + (size_t)s * F2 + lane * 4);
            acc.x += v.x * norm;
            acc.y += v.y * norm;
            acc.z += v.z * norm;
            acc.w += v.w * norm;
        }
    }

    if (act) {
        acc.x += b2[lane * 4 + 0];
        acc.y += b2[lane * 4 + 1];
        acc.z += b2[lane * 4 + 2];
        acc.w += b2[lane * 4 + 3];
    }

    float m = act ? fmaxf(fmaxf(acc.x, acc.y), fmaxf(acc.z, acc.w)) : -INFINITY;
    #pragma unroll
    for (int o = 16; o; o >>= 1) m = fmaxf(m, __shfl_xor_sync(0xFFFFFFFFu, m, o));
    float s = act ? (expf(acc.x - m) + expf(acc.y - m) +
                     expf(acc.z - m) + expf(acc.w - m)) : 0.f;
    #pragma unroll
    for (int o = 16; o; o >>= 1) s += __shfl_xor_sync(0xFFFFFFFFu, s, o);
    float l = m + logf(s);

    if (act) {
        float4 r = make_float4(acc.x - l, acc.y - l, acc.z - l, acc.w - l);
        *(float4*)(out + (size_t)node * F2 + lane * 4) = r;
    }
}

extern "C" void kernel_launch(void* const* d_in, const int* in_sizes, int n_in,
                              void* d_out, int out_size) {
    const float* x   = (const float*)d_in[0];
    const void*  ei  = d_in[1];
    const float* W1  = (const float*)d_in[2];
    const float* b1  = (const float*)d_in[3];
    const float* W2  = (const float*)d_in[4];
    const float* b2  = (const float*)d_in[5];
    float*       out = (float*)d_out;

    // dtype-agnostic edge decode
    k_detect  <<<1, 1>>>((const unsigned int*)ei);
    k_convert <<<(2 * NE + 255) / 256, 256>>>(ei);

    // CSR build + normalization
    k_zero_cnt<<<(NN + 255) / 256, 256>>>();
    k_count   <<<(NE + 255) / 256, 256>>>();
    k_scanA   <<<NB_SCAN, 256>>>();
    k_scanB   <<<1, 256>>>();
    k_scanC   <<<(NN + 255) / 256, 256>>>();
    k_fill    <<<(NE + 255) / 256, 256>>>();

    // layer 1
    k_gemm1   <<<(NN + 127) / 128, 256>>>(x, W1);
    k_gather1 <<<(int)(((long long)NN * 32 + 255) / 256), 256>>>();

    // layer 2 (+ fused bias2 + log_softmax)
    k_gemm2       <<<(NN + 63) / 64, 128>>>(W2, b1);
    k_gather2_lsm <<<(int)(((long long)NN * 32 + 255) / 256), 256>>>(b2, out);
}